// round 1
// baseline (speedup 1.0000x reference)
#include <cuda_runtime.h>
#include <math.h>
#include <float.h>

#define BB 8
#define NS 300
#define NT 100
#define CC 512
// JV on transposed problem: N rows (targets), M cols (sources)
#define JV_N NT
#define JV_M NS
#define HTHREADS 320
#define NWARPS (HTHREADS / 32)

__device__ float g_lse[BB * NS];
__device__ float g_cost[BB * NT * NS];   // [b][t][s]

// ---------------------------------------------------------------------------
// Kernel 1: logsumexp over class dim for every (b, s) row.
// ---------------------------------------------------------------------------
__global__ void lse_kernel(const float* __restrict__ logits) {
    int row = blockIdx.x;                 // b*NS + s
    const float* x = logits + (size_t)row * CC;
    int t = threadIdx.x;                  // 128 threads
    __shared__ float red[128];

    float m = -FLT_MAX;
    for (int i = t; i < CC; i += 128) m = fmaxf(m, x[i]);
    red[t] = m;
    __syncthreads();
    for (int o = 64; o > 0; o >>= 1) {
        if (t < o) red[t] = fmaxf(red[t], red[t + o]);
        __syncthreads();
    }
    m = red[0];
    __syncthreads();

    float s = 0.f;
    for (int i = t; i < CC; i += 128) s += expf(x[i] - m);
    red[t] = s;
    __syncthreads();
    for (int o = 64; o > 0; o >>= 1) {
        if (t < o) red[t] += red[t + o];
        __syncthreads();
    }
    if (t == 0) g_lse[row] = m + logf(red[0]);
}

// ---------------------------------------------------------------------------
// Kernel 2: pairwise cost  cost[b][t][s] = CE + 10*(1-GIOU) + L1
// grid (NT, B), block NS threads; thread = source index s.
// ---------------------------------------------------------------------------
__global__ void cost_kernel(const float* __restrict__ logits,
                            const float* __restrict__ sb,
                            const float* __restrict__ tb,
                            const int*   __restrict__ tgt) {
    int t = blockIdx.x;
    int b = blockIdx.y;
    int s = threadIdx.x;
    if (s >= NS) return;

    int cls = tgt[b * NT + t];
    float lse = g_lse[b * NS + s];
    float lg  = logits[((size_t)(b * NS + s)) * CC + cls];
    float ce  = lse - lg;

    const float* a  = sb + ((size_t)(b * NS + s)) * 4;
    const float* bx = tb + ((size_t)(b * NT + t)) * 4;
    float ax1 = a[0],  ay1 = a[1],  ax2 = a[2],  ay2 = a[3];
    float bx1 = bx[0], by1 = bx[1], bx2 = bx[2], by2 = bx[3];

    float l1 = 0.25f * (fabsf(ax1 - bx1) + fabsf(ay1 - by1) +
                        fabsf(ax2 - bx2) + fabsf(ay2 - by2));

    float ix1 = fmaxf(ax1, bx1), iy1 = fmaxf(ay1, by1);
    float ix2 = fminf(ax2, bx2), iy2 = fminf(ay2, by2);
    float inter = fmaxf(ix2 - ix1, 0.f) * fmaxf(iy2 - iy1, 0.f);
    float aa = (ax2 - ax1) * (ay2 - ay1);
    float ab = (bx2 - bx1) * (by2 - by1);
    float un = aa + ab - inter;
    float iou = inter / un;
    float ex1 = fminf(ax1, bx1), ey1 = fminf(ay1, by1);
    float ex2 = fmaxf(ax2, bx2), ey2 = fmaxf(ay2, by2);
    float encl = (ex2 - ex1) * (ey2 - ey1);
    float giou = iou - (encl - un) / encl;

    g_cost[(b * NT + t) * NS + s] = ce + 10.f * (1.f - giou) + l1;
}

// ---------------------------------------------------------------------------
// Kernel 3: Jonker-Volgenant (e-maxx) on the transposed 100x300 problem.
// One block per batch. Thread j owns column j (source). Duals in double to
// bit-match the reference's float64 decision sequence.
// ---------------------------------------------------------------------------
// Shared layout (bytes):
//   double v[M+1], minv[M+1], u[N+1], wbest[16], s_dbl[2]   = 721*8  = 5768
//   float  sc[N*M]                                           = 30000*4 = 120000
//   int    p[M+1], way[M+1], used[M+1], wj[16], s_int[4]    = 923*4  = 3692
#define JV_SMEM_BYTES (5768 + 120000 + 3692)

__global__ void __launch_bounds__(HTHREADS, 1)
hungarian_kernel(float* __restrict__ out) {
    int b   = blockIdx.x;
    int tid = threadIdx.x;
    int lane = tid & 31, warp = tid >> 5;

    extern __shared__ unsigned char smem_raw[];
    double* v     = (double*)smem_raw;            // M+1
    double* minv  = v + (JV_M + 1);               // M+1
    double* u     = minv + (JV_M + 1);            // N+1
    double* wbest = u + (JV_N + 1);               // 16
    double* s_dbl = wbest + 16;                   // [0]=u[i0], [1]=delta
    float*  sc    = (float*)(s_dbl + 2);          // N*M
    int*    p     = (int*)(sc + JV_N * JV_M);     // M+1
    int*    way   = p + (JV_M + 1);               // M+1
    int*    used  = way + (JV_M + 1);             // M+1
    int*    wj    = used + (JV_M + 1);            // 16
    int*    s_int = wj + 16;                      // [0]=i0 [1]=j0 [2]=j1

    // Stage full cost matrix for this batch into SMEM
    const float* gc = g_cost + (size_t)b * JV_N * JV_M;
    for (int k = tid; k < JV_N * JV_M; k += HTHREADS) sc[k] = gc[k];
    for (int k = tid; k <= JV_M; k += HTHREADS) { v[k] = 0.0; p[k] = 0; }
    for (int k = tid; k <= JV_N; k += HTHREADS) u[k] = 0.0;
    __syncthreads();

    for (int i = 1; i <= JV_N; ++i) {
        for (int k = tid; k <= JV_M; k += HTHREADS) { minv[k] = DBL_MAX; used[k] = 0; }
        if (tid == 0) { p[0] = i; s_int[1] = 0; }
        __syncthreads();

        while (true) {
            if (tid == 0) {
                int j0 = s_int[1];
                used[j0] = 1;
                int i0 = p[j0];
                s_int[0] = i0;
                s_dbl[0] = u[i0];
            }
            __syncthreads();
            int i0 = s_int[0];
            int j0 = s_int[1];
            double ui0 = s_dbl[0];

            int j = tid + 1;
            double best = DBL_MAX;
            int bestj = -1;
            if (j <= JV_M && !used[j]) {
                double cur = (double)sc[(i0 - 1) * JV_M + (j - 1)] - ui0 - v[j];
                if (cur < minv[j]) { minv[j] = cur; way[j] = j0; }
                best = minv[j];
                bestj = j;
            }
            // warp argmin (first-index tie-break via unsigned compare: -1 -> max)
            for (int o = 16; o > 0; o >>= 1) {
                double ob = __shfl_down_sync(0xffffffffu, best, o);
                int    oj = __shfl_down_sync(0xffffffffu, bestj, o);
                if (ob < best || (ob == best && (unsigned)oj < (unsigned)bestj)) {
                    best = ob; bestj = oj;
                }
            }
            if (lane == 0) { wbest[warp] = best; wj[warp] = bestj; }
            __syncthreads();
            if (tid == 0) {
                double bb = wbest[0]; int bj = wj[0];
                for (int w = 1; w < NWARPS; ++w) {
                    double ob = wbest[w]; int oj = wj[w];
                    if (ob < bb || (ob == bb && (unsigned)oj < (unsigned)bj)) {
                        bb = ob; bj = oj;
                    }
                }
                s_dbl[1] = bb;
                s_int[2] = bj;
            }
            __syncthreads();
            double delta = s_dbl[1];
            int j1 = s_int[2];

            if (tid == 0) { u[p[0]] += delta; v[0] -= delta; }
            if (j <= JV_M) {
                if (used[j]) { u[p[j]] += delta; v[j] -= delta; }
                else          minv[j] -= delta;
            }
            if (tid == 0) s_int[1] = j1;
            __syncthreads();
            if (p[j1] == 0) break;
        }

        // augment (serial chain, thread 0)
        if (tid == 0) {
            int j0 = s_int[1];
            while (j0) { int jw = way[j0]; p[j0] = p[jw]; j0 = jw; }
        }
        __syncthreads();
    }

    // total assigned cost; mean over NT kept pairs
    double local = 0.0;
    for (int j = tid + 1; j <= JV_M; j += HTHREADS)
        if (p[j]) local += (double)sc[(p[j] - 1) * JV_M + (j - 1)];
    for (int o = 16; o > 0; o >>= 1)
        local += __shfl_down_sync(0xffffffffu, local, o);
    if (lane == 0) wbest[warp] = local;
    __syncthreads();
    if (tid == 0) {
        double tot = 0.0;
        for (int w = 0; w < NWARPS; ++w) tot += wbest[w];
        out[b] = (float)(tot / (double)NT);
    }
}

// ---------------------------------------------------------------------------
extern "C" void kernel_launch(void* const* d_in, const int* in_sizes, int n_in,
                              void* d_out, int out_size) {
    const float* logits = nullptr;
    const float* sb = nullptr;
    const float* tb = nullptr;
    const int*   tgt = nullptr;
    for (int i = 0; i < n_in; ++i) {
        switch (in_sizes[i]) {
            case BB * NS * CC: logits = (const float*)d_in[i]; break;
            case BB * NS * 4:  sb     = (const float*)d_in[i]; break;
            case BB * NT * 4:  tb     = (const float*)d_in[i]; break;
            case BB * NT:      tgt    = (const int*)d_in[i];   break;
            default: break;
        }
    }
    float* out = (float*)d_out;

    lse_kernel<<<BB * NS, 128>>>(logits);
    cost_kernel<<<dim3(NT, BB), NS>>>(logits, sb, tb, tgt);

    cudaFuncSetAttribute(hungarian_kernel,
                         cudaFuncAttributeMaxDynamicSharedMemorySize,
                         JV_SMEM_BYTES);
    hungarian_kernel<<<BB, HTHREADS, JV_SMEM_BYTES>>>(out);
}